// round 13
// baseline (speedup 1.0000x reference)
#include <cuda_runtime.h>
#include <cuda_fp16.h>
#include <math.h>

#define Bb 8
#define Hh 16
#define Nn 512
#define Dk 64
#define Dm 1024

typedef unsigned long long ull;

__device__ __forceinline__ ull f2dup(float a) {
    ull r; asm("mov.b64 %0,{%1,%1};" : "=l"(r) : "f"(a)); return r;
}
__device__ __forceinline__ float2 unpack2(ull a) {
    float2 f; asm("mov.b64 {%0,%1},%2;" : "=f"(f.x), "=f"(f.y) : "l"(a)); return f;
}
__device__ __forceinline__ ull ffma2(ull a, ull b, ull c) {
    ull d; asm("fma.rn.f32x2 %0,%1,%2,%3;" : "=l"(d) : "l"(a), "l"(b), "l"(c)); return d;
}
__device__ __forceinline__ ull fmul2(ull a, ull b) {
    ull d; asm("mul.rn.f32x2 %0,%1,%2;" : "=l"(d) : "l"(a), "l"(b)); return d;
}

__device__ float g_q[Bb*Hh*Nn*Dk];
__device__ float g_k[Bb*Hh*Nn*Dk];
__device__ float g_v[Bb*Hh*Nn*Dk];
__device__ __align__(16) __half g_g16[(size_t)Bb*Hh*Nn*Nn]; // g=(b,h,i,j)
__device__ float g_attn[Bb*Nn*Hh*Dk];
__device__ float g_bf[Bb*Nn*40];

// ---------------- GEMM core (BK=16 double-buffered, FFMA2) -----------------
__device__ __forceinline__ void gemm_body(const float* __restrict__ A,
                                          const float* __restrict__ W,
                                          const float* __restrict__ bias,
                                          float* __restrict__ C, int remap,
                                          int m0, int n0,
                                          float As[2][16][128], float Bs[2][16][128]) {
    int tid = threadIdx.x;
    int tx = tid & 15, ty = tid >> 4;
    int lr = tid >> 1, lc = (tid & 1) * 8;
    const float* Ap = A + (size_t)(m0 + lr) * 1024 + lc;
    const float* Wp = W + (size_t)(n0 + lr) * 1024 + lc;

    ull acc[8][4];
#pragma unroll
    for (int i = 0; i < 8; i++)
#pragma unroll
        for (int p = 0; p < 4; p++) acc[i][p] = 0ull;

    float av[8], wv[8];
    {
        float4 x0 = *(const float4*)Ap, x1 = *(const float4*)(Ap+4);
        float4 y0 = *(const float4*)Wp, y1 = *(const float4*)(Wp+4);
        av[0]=x0.x;av[1]=x0.y;av[2]=x0.z;av[3]=x0.w;av[4]=x1.x;av[5]=x1.y;av[6]=x1.z;av[7]=x1.w;
        wv[0]=y0.x;wv[1]=y0.y;wv[2]=y0.z;wv[3]=y0.w;wv[4]=y1.x;wv[5]=y1.y;wv[6]=y1.z;wv[7]=y1.w;
    }
#pragma unroll
    for (int j = 0; j < 8; j++) { As[0][lc+j][lr] = av[j]; Bs[0][lc+j][lr] = wv[j]; }
    __syncthreads();

#pragma unroll 1
    for (int t = 0; t < 64; t++) {
        int cur = t & 1;
        if (t < 63) {
            float4 x0 = *(const float4*)(Ap+(t+1)*16), x1 = *(const float4*)(Ap+(t+1)*16+4);
            float4 y0 = *(const float4*)(Wp+(t+1)*16), y1 = *(const float4*)(Wp+(t+1)*16+4);
            av[0]=x0.x;av[1]=x0.y;av[2]=x0.z;av[3]=x0.w;av[4]=x1.x;av[5]=x1.y;av[6]=x1.z;av[7]=x1.w;
            wv[0]=y0.x;wv[1]=y0.y;wv[2]=y0.z;wv[3]=y0.w;wv[4]=y1.x;wv[5]=y1.y;wv[6]=y1.z;wv[7]=y1.w;
        }
#pragma unroll
        for (int kk = 0; kk < 16; kk++) {
            float4 a0 = *(const float4*)&As[cur][kk][ty*4];
            float4 a1 = *(const float4*)&As[cur][kk][64+ty*4];
            ull ad[8] = {f2dup(a0.x),f2dup(a0.y),f2dup(a0.z),f2dup(a0.w),
                         f2dup(a1.x),f2dup(a1.y),f2dup(a1.z),f2dup(a1.w)};
            ulonglong2 b0 = *(const ulonglong2*)&Bs[cur][kk][tx*4];
            ulonglong2 b1 = *(const ulonglong2*)&Bs[cur][kk][64+tx*4];
            ull bp[4] = {b0.x, b0.y, b1.x, b1.y};
#pragma unroll
            for (int i = 0; i < 8; i++)
#pragma unroll
                for (int p = 0; p < 4; p++)
                    acc[i][p] = ffma2(ad[i], bp[p], acc[i][p]);
        }
        if (t < 63) {
#pragma unroll
            for (int j = 0; j < 8; j++) { As[cur^1][lc+j][lr] = av[j]; Bs[cur^1][lc+j][lr] = wv[j]; }
        }
        __syncthreads();
    }
#pragma unroll
    for (int i = 0; i < 8; i++) {
        int mrow = m0 + ((i < 4) ? (ty*4+i) : (64+ty*4+(i-4)));
#pragma unroll
        for (int jq = 0; jq < 2; jq++) {
            int ncol = n0 + ((jq==0) ? (tx*4) : (64+tx*4));
            float2 u0 = unpack2(acc[i][jq*2+0]);
            float2 u1 = unpack2(acc[i][jq*2+1]);
            float4 v;
            v.x = u0.x + bias[ncol+0]; v.y = u0.y + bias[ncol+1];
            v.z = u1.x + bias[ncol+2]; v.w = u1.y + bias[ncol+3];
            if (remap) {
                int bb = mrow>>9, n = mrow&511, hh = ncol>>6, d = ncol&63;
                *(float4*)&C[(((size_t)bb*Hh+hh)*Nn+n)*Dk+d] = v;
            } else {
                *(float4*)&C[(size_t)mrow*1024+ncol] = v;
            }
        }
    }
}

__global__ __launch_bounds__(256) void sgemm_qkv(const float* __restrict__ Aq,
                                                 const float* __restrict__ Ak,
                                                 const float* __restrict__ Av,
                                                 const float* __restrict__ Wq,
                                                 const float* __restrict__ Wk,
                                                 const float* __restrict__ Wv,
                                                 const float* __restrict__ bq,
                                                 const float* __restrict__ bk,
                                                 const float* __restrict__ bv,
                                                 int z0) {
    __shared__ __align__(16) float As[2][16][128];
    __shared__ __align__(16) float Bs[2][16][128];
    int z = z0 + blockIdx.z;
    const float* A = (z == 0) ? Aq : (z == 1) ? Ak : Av;
    const float* W = (z == 0) ? Wq : (z == 1) ? Wk : Wv;
    const float* bias = (z == 0) ? bq : (z == 1) ? bk : bv;
    float* C = (z == 0) ? g_q : (z == 1) ? g_k : g_v;
    gemm_body(A, W, bias, C, 1, blockIdx.y*128, blockIdx.x*128, As, Bs);
}

__global__ __launch_bounds__(256) void sgemm_tn(const float* __restrict__ A,
                                                const float* __restrict__ W,
                                                const float* __restrict__ bias,
                                                float* __restrict__ C) {
    __shared__ __align__(16) float As[2][16][128];
    __shared__ __align__(16) float Bs[2][16][128];
    gemm_body(A, W, bias, C, 0, blockIdx.y*128, blockIdx.x*128, As, Bs);
}

// ---------------- per-box features -----------------------------------------
__global__ __launch_bounds__(512) void box_feat_kernel(const float* __restrict__ boxes) {
    int b = blockIdx.x, i = threadIdx.x;
    const float* p = boxes + ((size_t)b*Nn+i)*4;
    float x0=p[0], y0=p[1], x1=p[2], y1=p[3];
    float cx=0.5f*(x0+x1), cy=0.5f*(y0+y1);
    float w=x1-x0+1.0f, h=y1-y0+1.0f;
    float lw=__logf(w), lh=__logf(h);
    float* o = g_bf + ((size_t)b*Nn+i)*40;
    o[0]=cx; o[1]=cy; o[2]=lw; o[3]=lh;
    const float dm[8] = {1.0f,0.421696503429f,0.177827941004f,0.0749894209332f,
                         0.0316227766017f,0.0133352143216f,0.00562341325190f,0.00237137370566f};
#pragma unroll
    for (int f = 0; f < 8; f++) {
        float sw, cw, sh, ch;
        __sincosf(100.0f*dm[f]*lw, &sw, &cw);
        __sincosf(100.0f*dm[f]*lh, &sh, &ch);
        *(float4*)&o[4 + f*4] = make_float4(sw, cw, sh, ch);
    }
}

// ---------------- geometry bias: smem-staged full-line writes --------------
// j-loop NOT unrolled (one live acc[8]) to stay within register budget.
__global__ __launch_bounds__(256) void geo_bias_kernel(const float* __restrict__ Wg,
                                                       const float* __restrict__ bg) {
    __shared__ __align__(16) ull Wsp[32][8];
    __shared__ __align__(16) ull Wcp[32][8];
    __shared__ ull bgp[8];
    __shared__ __align__(16) __half hbuf[16][512];   // 16 KB staging tile
    int i = blockIdx.x, b = blockIdx.y;
    int tid = threadIdx.x;

    for (int t = tid; t < 32*8; t += 256) {
        int idx = t >> 3, p = t & 7;
        float lo_s = Wg[(2*p)*64 + idx],     hi_s = Wg[(2*p+1)*64 + idx];
        float lo_c = Wg[(2*p)*64 + 32+idx],  hi_c = Wg[(2*p+1)*64 + 32+idx];
        ull us, uc;
        asm("mov.b64 %0,{%1,%2};" : "=l"(us) : "f"(lo_s), "f"(hi_s));
        asm("mov.b64 %0,{%1,%2};" : "=l"(uc) : "f"(lo_c), "f"(hi_c));
        Wsp[idx][p] = us; Wcp[idx][p] = uc;
    }
    if (tid < 8) {
        ull ub;
        asm("mov.b64 %0,{%1,%2};" : "=l"(ub) : "f"(bg[2*tid]), "f"(bg[2*tid+1]));
        bgp[tid] = ub;
    }

    const float* fi = g_bf + ((size_t)b*Nn+i)*40;
    float cxi = fi[0], cyi = fi[1], lwi = fi[2], lhi = fi[3];
    float swi[8], cwi[8], shi[8], chi[8];
#pragma unroll
    for (int f = 0; f < 8; f++) {
        float4 v = *(const float4*)&fi[4 + f*4];
        swi[f]=v.x; cwi[f]=v.y; shi[f]=v.z; chi[f]=v.w;
    }
    __syncthreads();

    const float dm[8] = {1.0f,0.421696503429f,0.177827941004f,0.0749894209332f,
                         0.0316227766017f,0.0133352143216f,0.00562341325190f,0.00237137370566f};
    const float C0 = -6.90775527898f;

#pragma unroll 1
    for (int j = tid; j < Nn; j += 256) {
        const float* fj = g_bf + ((size_t)b*Nn+j)*40;
        float4 h0 = *(const float4*)fj;
        float ux = fmaxf(__logf(fabsf(cxi - h0.x)) - lwi, C0);
        float uy = fmaxf(__logf(fabsf(cyi - h0.y)) - lhi, C0);

        ull acc[8];
#pragma unroll
        for (int p = 0; p < 8; p++) acc[p] = bgp[p];

#pragma unroll
        for (int f = 0; f < 8; f++) {
            float sx, cx_, sy, cy_;
            __sincosf(100.0f*dm[f]*ux, &sx, &cx_);
            __sincosf(100.0f*dm[f]*uy, &sy, &cy_);
            float4 tj = *(const float4*)&fj[4 + f*4];
            float sw_ = swi[f]*tj.y - cwi[f]*tj.x;
            float cw_ = cwi[f]*tj.y + swi[f]*tj.x;
            float sh_ = shi[f]*tj.w - chi[f]*tj.z;
            float ch_ = chi[f]*tj.w + shi[f]*tj.z;
            float sv[4] = {sx, sy, sw_, sh_};
            float cv[4] = {cx_, cy_, cw_, ch_};
#pragma unroll
            for (int c = 0; c < 4; c++) {
                int idx = c*8 + f;
                ull sd = f2dup(sv[c]), cd = f2dup(cv[c]);
                ulonglong2 s0 = *(const ulonglong2*)&Wsp[idx][0];
                ulonglong2 s1 = *(const ulonglong2*)&Wsp[idx][2];
                ulonglong2 s2 = *(const ulonglong2*)&Wsp[idx][4];
                ulonglong2 s3 = *(const ulonglong2*)&Wsp[idx][6];
                acc[0] = ffma2(sd, s0.x, acc[0]); acc[1] = ffma2(sd, s0.y, acc[1]);
                acc[2] = ffma2(sd, s1.x, acc[2]); acc[3] = ffma2(sd, s1.y, acc[3]);
                acc[4] = ffma2(sd, s2.x, acc[4]); acc[5] = ffma2(sd, s2.y, acc[5]);
                acc[6] = ffma2(sd, s3.x, acc[6]); acc[7] = ffma2(sd, s3.y, acc[7]);
                ulonglong2 c0 = *(const ulonglong2*)&Wcp[idx][0];
                ulonglong2 c1 = *(const ulonglong2*)&Wcp[idx][2];
                ulonglong2 c2 = *(const ulonglong2*)&Wcp[idx][4];
                ulonglong2 c3 = *(const ulonglong2*)&Wcp[idx][6];
                acc[0] = ffma2(cd, c0.x, acc[0]); acc[1] = ffma2(cd, c0.y, acc[1]);
                acc[2] = ffma2(cd, c1.x, acc[2]); acc[3] = ffma2(cd, c1.y, acc[3]);
                acc[4] = ffma2(cd, c2.x, acc[4]); acc[5] = ffma2(cd, c2.y, acc[5]);
                acc[6] = ffma2(cd, c3.x, acc[6]); acc[7] = ffma2(cd, c3.y, acc[7]);
            }
        }
#pragma unroll
        for (int p = 0; p < 8; p++) {
            float2 u = unpack2(acc[p]);
            hbuf[2*p][j]   = __float2half_rn(fmaxf(u.x, 1e-6f));
            hbuf[2*p+1][j] = __float2half_rn(fmaxf(u.y, 1e-6f));
        }
    }
    __syncthreads();

    // write phase: 16 head-rows x 1 KB contiguous; every store fills whole 128B lines
    size_t rowstride = (size_t)Nn*Nn;
    __half* gout = &g_g16[((size_t)b*Hh*Nn + i)*Nn];
#pragma unroll 1
    for (int t = tid; t < 1024; t += 256) {
        int h = t >> 6, seg = t & 63;
        ((uint4*)(gout + (size_t)h*rowstride))[seg] = ((const uint4*)&hbuf[h][0])[seg];
    }
}

// ---------------- flash attention (unchanged) ------------------------------
__global__ __launch_bounds__(128) void attn_kernel() {
    extern __shared__ float sh[];
    float* Qs = sh;
    float* Kt = sh + 64*68;
    float* Vt = Kt + 64*68;
    float* Pt = Vt + 64*68;

    int bh = blockIdx.y;
    int b = bh >> 4, h = bh & 15;
    int q0 = blockIdx.x * 64;
    const float* Qg = g_q + ((size_t)bh*Nn + q0)*Dk;
    const float* Kg = g_k + (size_t)bh*Nn*Dk;
    const float* Vg = g_v + (size_t)bh*Nn*Dk;
    const __half* Gg = g_g16 + ((size_t)bh*Nn + q0)*Nn;

    int tid = threadIdx.x;
    int tx = tid & 7, qs = tid >> 3;

    for (int tt = tid; tt < 256; tt += 128) {
        int qb = (tt & 15)*4, d0 = (tt >> 4)*4;
        float4 r0 = *(const float4*)&Qg[(qb+0)*64+d0];
        float4 r1 = *(const float4*)&Qg[(qb+1)*64+d0];
        float4 r2 = *(const float4*)&Qg[(qb+2)*64+d0];
        float4 r3 = *(const float4*)&Qg[(qb+3)*64+d0];
        *(float4*)&Qs[(d0+0)*68+qb] = make_float4(r0.x,r1.x,r2.x,r3.x);
        *(float4*)&Qs[(d0+1)*68+qb] = make_float4(r0.y,r1.y,r2.y,r3.y);
        *(float4*)&Qs[(d0+2)*68+qb] = make_float4(r0.z,r1.z,r2.z,r3.z);
        *(float4*)&Qs[(d0+3)*68+qb] = make_float4(r0.w,r1.w,r2.w,r3.w);
    }

    float m[4], l[4];
    ull o[4][4];
#pragma unroll
    for (int i = 0; i < 4; i++) {
        m[i] = -1e30f; l[i] = 0.f;
#pragma unroll
        for (int p = 0; p < 4; p++) o[i][p] = 0ull;
    }

    for (int kt = 0; kt < 8; kt++) {
        __syncthreads();
        for (int tt = tid; tt < 256; tt += 128) {
            int kb = (tt & 15)*4, d0 = (tt >> 4)*4;
            const float* Kb = Kg + (size_t)(kt*64)*Dk;
            float4 r0 = *(const float4*)&Kb[(kb+0)*64+d0];
            float4 r1 = *(const float4*)&Kb[(kb+1)*64+d0];
            float4 r2 = *(const float4*)&Kb[(kb+2)*64+d0];
            float4 r3 = *(const float4*)&Kb[(kb+3)*64+d0];
            *(float4*)&Kt[(d0+0)*68+kb] = make_float4(r0.x,r1.x,r2.x,r3.x);
            *(float4*)&Kt[(d0+1)*68+kb] = make_float4(r0.y,r1.y,r2.y,r3.y);
            *(float4*)&Kt[(d0+2)*68+kb] = make_float4(r0.z,r1.z,r2.z,r3.z);
            *(float4*)&Kt[(d0+3)*68+kb] = make_float4(r0.w,r1.w,r2.w,r3.w);
        }
        for (int i = tid; i < 1024; i += 128) {
            int r = i >> 4, c = (i & 15)*4;
            *(float4*)&Vt[r*68+c] = *(const float4*)&Vg[(size_t)(kt*64+r)*64+c];
        }
        __syncthreads();

        ull acc[4][4];
#pragma unroll
        for (int i = 0; i < 4; i++)
#pragma unroll
            for (int p = 0; p < 4; p++) acc[i][p] = 0ull;
#pragma unroll 4
        for (int d = 0; d < 64; d++) {
            float4 qv = *(const float4*)&Qs[d*68 + qs*4];
            ull qd[4] = {f2dup(qv.x), f2dup(qv.y), f2dup(qv.z), f2dup(qv.w)};
            ulonglong2 k0 = *(const ulonglong2*)&Kt[d*68 + tx*8];
            ulonglong2 k1 = *(const ulonglong2*)&Kt[d*68 + tx*8 + 4];
            ull kp[4] = {k0.x, k0.y, k1.x, k1.y};
#pragma unroll
            for (int i = 0; i < 4; i++)
#pragma unroll
                for (int p = 0; p < 4; p++)
                    acc[i][p] = ffma2(qd[i], kp[p], acc[i][p]);
        }

#pragma unroll
        for (int qq = 0; qq < 4; qq++) {
            float s[8];
#pragma unroll
            for (int p = 0; p < 4; p++) {
                float2 u = unpack2(acc[qq][p]);
                s[2*p] = u.x*0.125f; s[2*p+1] = u.y*0.125f;
            }
            float mt = s[0];
#pragma unroll
            for (int j = 1; j < 8; j++) mt = fmaxf(mt, s[j]);
            mt = fmaxf(mt, __shfl_xor_sync(0xffffffffu, mt, 1, 8));
            mt = fmaxf(mt, __shfl_xor_sync(0xffffffffu, mt, 2, 8));
            mt = fmaxf(mt, __shfl_xor_sync(0xffffffffu, mt, 4, 8));
            float mn = fmaxf(m[qq], mt);
            float resc = __expf(m[qq] - mn);
            m[qq] = mn;
            l[qq] *= resc;
            ull rd = f2dup(resc);
#pragma unroll
            for (int p = 0; p < 4; p++) o[qq][p] = fmul2(o[qq][p], rd);

            const __half* gp = Gg + (size_t)(qs*4+qq)*Nn + kt*64 + tx*8;
            uint4 gv = *(const uint4*)gp;
            float2 g0 = __half22float2(*(__half2*)&gv.x);
            float2 g1 = __half22float2(*(__half2*)&gv.y);
            float2 g2 = __half22float2(*(__half2*)&gv.z);
            float2 g3 = __half22float2(*(__half2*)&gv.w);
            float w0 = g0.x*__expf(s[0]-mn), w1 = g0.y*__expf(s[1]-mn);
            float w2 = g1.x*__expf(s[2]-mn), w3 = g1.y*__expf(s[3]-mn);
            float w4 = g2.x*__expf(s[4]-mn), w5 = g2.y*__expf(s[5]-mn);
            float w6 = g3.x*__expf(s[6]-mn), w7 = g3.y*__expf(s[7]-mn);
            float ps = ((w0+w1)+(w2+w3)) + ((w4+w5)+(w6+w7));
            ps += __shfl_xor_sync(0xffffffffu, ps, 1, 8);
            ps += __shfl_xor_sync(0xffffffffu, ps, 2, 8);
            ps += __shfl_xor_sync(0xffffffffu, ps, 4, 8);
            l[qq] += ps;
            *(float4*)&Pt[(qs*4+qq)*72 + tx*8]     = make_float4(w0,w1,w2,w3);
            *(float4*)&Pt[(qs*4+qq)*72 + tx*8 + 4] = make_float4(w4,w5,w6,w7);
        }
        __syncthreads();

#pragma unroll 4
        for (int k = 0; k < 64; k++) {
            ull pd[4];
#pragma unroll
            for (int qq = 0; qq < 4; qq++) pd[qq] = f2dup(Pt[(qs*4+qq)*72 + k]);
            ulonglong2 v0 = *(const ulonglong2*)&Vt[k*68 + tx*8];
            ulonglong2 v1 = *(const ulonglong2*)&Vt[k*68 + tx*8 + 4];
            ull vp[4] = {v0.x, v0.y, v1.x, v1.y};
#pragma unroll
            for (int i = 0; i < 4; i++)
#pragma unroll
                for (int p = 0; p < 4; p++)
                    o[i][p] = ffma2(pd[i], vp[p], o[i][p]);
        }
    }

#pragma unroll
    for (int qq = 0; qq < 4; qq++) {
        float inv = 1.0f / l[qq];
        int row = q0 + qs*4 + qq;
        float2 u0 = unpack2(o[qq][0]), u1 = unpack2(o[qq][1]);
        float2 u2 = unpack2(o[qq][2]), u3 = unpack2(o[qq][3]);
        size_t base = ((size_t)b*Nn+row)*Dm + h*64 + tx*8;
        *(float4*)&g_attn[base]   = make_float4(u0.x*inv, u0.y*inv, u1.x*inv, u1.y*inv);
        *(float4*)&g_attn[base+4] = make_float4(u2.x*inv, u2.y*inv, u3.x*inv, u3.y*inv);
    }
}

// ---------------------------------------------------------------------------
extern "C" void kernel_launch(void* const* d_in, const int* in_sizes, int n_in,
                              void* d_out, int out_size) {
    (void)in_sizes; (void)n_in; (void)out_size;
    const float* queries = (const float*)d_in[0];
    const float* keys    = (const float*)d_in[1];
    const float* values  = (const float*)d_in[2];
    const float* boxes   = (const float*)d_in[3];
    const float* Wq = (const float*)d_in[4];
    const float* bq = (const float*)d_in[5];
    const float* Wk = (const float*)d_in[6];
    const float* bk = (const float*)d_in[7];
    const float* Wv = (const float*)d_in[8];
    const float* bv = (const float*)d_in[9];
    const float* Wo = (const float*)d_in[10];
    const float* bo = (const float*)d_in[11];
    const float* Wg = (const float*)d_in[12];
    const float* bg = (const float*)d_in[13];
    float* out = (float*)d_out;

    float *dattn = nullptr;
    cudaGetSymbolAddress((void**)&dattn, g_attn);

    size_t shb = (size_t)(64*68*3 + 64*72) * sizeof(float);
    cudaFuncSetAttribute(attn_kernel, cudaFuncAttributeMaxDynamicSharedMemorySize, (int)shb);

    dim3 gemm_grid(Dm/128, (Bb*Nn)/128);

    // launch order: box(1), q(2), kv(3), geo(4) <- ncu slot, attn(5), out(6)
    box_feat_kernel<<<Bb, 512>>>(boxes);
    sgemm_qkv<<<dim3(8, 32, 1), 256>>>(queries, keys, values, Wq, Wk, Wv, bq, bk, bv, 0);
    sgemm_qkv<<<dim3(8, 32, 2), 256>>>(queries, keys, values, Wq, Wk, Wv, bq, bk, bv, 1);
    geo_bias_kernel<<<dim3(Nn, Bb), 256>>>(Wg, bg);
    attn_kernel<<<dim3(Nn/64, Bb*Hh), 128, shb>>>();
    sgemm_tn<<<gemm_grid, 256>>>(dattn, Wo, bo, out);
}

// round 16
// speedup vs baseline: 1.0211x; 1.0211x over previous
#include <cuda_runtime.h>
#include <cuda_fp16.h>
#include <math.h>

#define Bb 8
#define Hh 16
#define Nn 512
#define Dk 64
#define Dm 1024

typedef unsigned long long ull;

__device__ __forceinline__ ull f2dup(float a) {
    ull r; asm("mov.b64 %0,{%1,%1};" : "=l"(r) : "f"(a)); return r;
}
__device__ __forceinline__ float2 unpack2(ull a) {
    float2 f; asm("mov.b64 {%0,%1},%2;" : "=f"(f.x), "=f"(f.y) : "l"(a)); return f;
}
__device__ __forceinline__ ull ffma2(ull a, ull b, ull c) {
    ull d; asm("fma.rn.f32x2 %0,%1,%2,%3;" : "=l"(d) : "l"(a), "l"(b), "l"(c)); return d;
}
__device__ __forceinline__ ull fmul2(ull a, ull b) {
    ull d; asm("mul.rn.f32x2 %0,%1,%2;" : "=l"(d) : "l"(a), "l"(b)); return d;
}

__device__ float g_q[Bb*Hh*Nn*Dk];
__device__ float g_k[Bb*Hh*Nn*Dk];
__device__ float g_v[Bb*Hh*Nn*Dk];
// NEW layout: (b, i, h, j) — each (b,i) owns one contiguous 16 KB chunk
__device__ __align__(16) __half g_g16[(size_t)Bb*Nn*Hh*Nn];
__device__ float g_attn[Bb*Nn*Hh*Dk];
__device__ float g_bf[Bb*Nn*40];

// ---------------- GEMM core (BK=16 double-buffered, FFMA2) -----------------
__device__ __forceinline__ void gemm_body(const float* __restrict__ A,
                                          const float* __restrict__ W,
                                          const float* __restrict__ bias,
                                          float* __restrict__ C, int remap,
                                          int m0, int n0,
                                          float As[2][16][128], float Bs[2][16][128]) {
    int tid = threadIdx.x;
    int tx = tid & 15, ty = tid >> 4;
    int lr = tid >> 1, lc = (tid & 1) * 8;
    const float* Ap = A + (size_t)(m0 + lr) * 1024 + lc;
    const float* Wp = W + (size_t)(n0 + lr) * 1024 + lc;

    ull acc[8][4];
#pragma unroll
    for (int i = 0; i < 8; i++)
#pragma unroll
        for (int p = 0; p < 4; p++) acc[i][p] = 0ull;

    float av[8], wv[8];
    {
        float4 x0 = *(const float4*)Ap, x1 = *(const float4*)(Ap+4);
        float4 y0 = *(const float4*)Wp, y1 = *(const float4*)(Wp+4);
        av[0]=x0.x;av[1]=x0.y;av[2]=x0.z;av[3]=x0.w;av[4]=x1.x;av[5]=x1.y;av[6]=x1.z;av[7]=x1.w;
        wv[0]=y0.x;wv[1]=y0.y;wv[2]=y0.z;wv[3]=y0.w;wv[4]=y1.x;wv[5]=y1.y;wv[6]=y1.z;wv[7]=y1.w;
    }
#pragma unroll
    for (int j = 0; j < 8; j++) { As[0][lc+j][lr] = av[j]; Bs[0][lc+j][lr] = wv[j]; }
    __syncthreads();

#pragma unroll 1
    for (int t = 0; t < 64; t++) {
        int cur = t & 1;
        if (t < 63) {
            float4 x0 = *(const float4*)(Ap+(t+1)*16), x1 = *(const float4*)(Ap+(t+1)*16+4);
            float4 y0 = *(const float4*)(Wp+(t+1)*16), y1 = *(const float4*)(Wp+(t+1)*16+4);
            av[0]=x0.x;av[1]=x0.y;av[2]=x0.z;av[3]=x0.w;av[4]=x1.x;av[5]=x1.y;av[6]=x1.z;av[7]=x1.w;
            wv[0]=y0.x;wv[1]=y0.y;wv[2]=y0.z;wv[3]=y0.w;wv[4]=y1.x;wv[5]=y1.y;wv[6]=y1.z;wv[7]=y1.w;
        }
#pragma unroll
        for (int kk = 0; kk < 16; kk++) {
            float4 a0 = *(const float4*)&As[cur][kk][ty*4];
            float4 a1 = *(const float4*)&As[cur][kk][64+ty*4];
            ull ad[8] = {f2dup(a0.x),f2dup(a0.y),f2dup(a0.z),f2dup(a0.w),
                         f2dup(a1.x),f2dup(a1.y),f2dup(a1.z),f2dup(a1.w)};
            ulonglong2 b0 = *(const ulonglong2*)&Bs[cur][kk][tx*4];
            ulonglong2 b1 = *(const ulonglong2*)&Bs[cur][kk][64+tx*4];
            ull bp[4] = {b0.x, b0.y, b1.x, b1.y};
#pragma unroll
            for (int i = 0; i < 8; i++)
#pragma unroll
                for (int p = 0; p < 4; p++)
                    acc[i][p] = ffma2(ad[i], bp[p], acc[i][p]);
        }
        if (t < 63) {
#pragma unroll
            for (int j = 0; j < 8; j++) { As[cur^1][lc+j][lr] = av[j]; Bs[cur^1][lc+j][lr] = wv[j]; }
        }
        __syncthreads();
    }
#pragma unroll
    for (int i = 0; i < 8; i++) {
        int mrow = m0 + ((i < 4) ? (ty*4+i) : (64+ty*4+(i-4)));
#pragma unroll
        for (int jq = 0; jq < 2; jq++) {
            int ncol = n0 + ((jq==0) ? (tx*4) : (64+tx*4));
            float2 u0 = unpack2(acc[i][jq*2+0]);
            float2 u1 = unpack2(acc[i][jq*2+1]);
            float4 v;
            v.x = u0.x + bias[ncol+0]; v.y = u0.y + bias[ncol+1];
            v.z = u1.x + bias[ncol+2]; v.w = u1.y + bias[ncol+3];
            if (remap) {
                int bb = mrow>>9, n = mrow&511, hh = ncol>>6, d = ncol&63;
                *(float4*)&C[(((size_t)bb*Hh+hh)*Nn+n)*Dk+d] = v;
            } else {
                *(float4*)&C[(size_t)mrow*1024+ncol] = v;
            }
        }
    }
}

__global__ __launch_bounds__(256) void sgemm_qkv(const float* __restrict__ Aq,
                                                 const float* __restrict__ Ak,
                                                 const float* __restrict__ Av,
                                                 const float* __restrict__ Wq,
                                                 const float* __restrict__ Wk,
                                                 const float* __restrict__ Wv,
                                                 const float* __restrict__ bq,
                                                 const float* __restrict__ bk,
                                                 const float* __restrict__ bv,
                                                 int z0) {
    __shared__ __align__(16) float As[2][16][128];
    __shared__ __align__(16) float Bs[2][16][128];
    int z = z0 + blockIdx.z;
    const float* A = (z == 0) ? Aq : (z == 1) ? Ak : Av;
    const float* W = (z == 0) ? Wq : (z == 1) ? Wk : Wv;
    const float* bias = (z == 0) ? bq : (z == 1) ? bk : bv;
    float* C = (z == 0) ? g_q : (z == 1) ? g_k : g_v;
    gemm_body(A, W, bias, C, 1, blockIdx.y*128, blockIdx.x*128, As, Bs);
}

__global__ __launch_bounds__(256) void sgemm_tn(const float* __restrict__ A,
                                                const float* __restrict__ W,
                                                const float* __restrict__ bias,
                                                float* __restrict__ C) {
    __shared__ __align__(16) float As[2][16][128];
    __shared__ __align__(16) float Bs[2][16][128];
    gemm_body(A, W, bias, C, 0, blockIdx.y*128, blockIdx.x*128, As, Bs);
}

// ---------------- per-box features -----------------------------------------
__global__ __launch_bounds__(512) void box_feat_kernel(const float* __restrict__ boxes) {
    int b = blockIdx.x, i = threadIdx.x;
    const float* p = boxes + ((size_t)b*Nn+i)*4;
    float x0=p[0], y0=p[1], x1=p[2], y1=p[3];
    float cx=0.5f*(x0+x1), cy=0.5f*(y0+y1);
    float w=x1-x0+1.0f, h=y1-y0+1.0f;
    float lw=__logf(w), lh=__logf(h);
    float* o = g_bf + ((size_t)b*Nn+i)*40;
    o[0]=cx; o[1]=cy; o[2]=lw; o[3]=lh;
    const float dm[8] = {1.0f,0.421696503429f,0.177827941004f,0.0749894209332f,
                         0.0316227766017f,0.0133352143216f,0.00562341325190f,0.00237137370566f};
#pragma unroll
    for (int f = 0; f < 8; f++) {
        float sw, cw, sh, ch;
        __sincosf(100.0f*dm[f]*lw, &sw, &cw);
        __sincosf(100.0f*dm[f]*lh, &sh, &ch);
        *(float4*)&o[4 + f*4] = make_float4(sw, cw, sh, ch);
    }
}

// ---------------- geometry bias: contiguous 16 KB per-block output ---------
__global__ __launch_bounds__(256) void geo_bias_kernel(const float* __restrict__ Wg,
                                                       const float* __restrict__ bg) {
    __shared__ __align__(16) ull Wsp[32][8];
    __shared__ __align__(16) ull Wcp[32][8];
    __shared__ ull bgp[8];
    __shared__ __align__(16) __half hbuf[16][512];   // 16 KB staging, (h, j)
    int i = blockIdx.x, b = blockIdx.y;
    int tid = threadIdx.x;

    for (int t = tid; t < 32*8; t += 256) {
        int idx = t >> 3, p = t & 7;
        float lo_s = Wg[(2*p)*64 + idx],     hi_s = Wg[(2*p+1)*64 + idx];
        float lo_c = Wg[(2*p)*64 + 32+idx],  hi_c = Wg[(2*p+1)*64 + 32+idx];
        ull us, uc;
        asm("mov.b64 %0,{%1,%2};" : "=l"(us) : "f"(lo_s), "f"(hi_s));
        asm("mov.b64 %0,{%1,%2};" : "=l"(uc) : "f"(lo_c), "f"(hi_c));
        Wsp[idx][p] = us; Wcp[idx][p] = uc;
    }
    if (tid < 8) {
        ull ub;
        asm("mov.b64 %0,{%1,%2};" : "=l"(ub) : "f"(bg[2*tid]), "f"(bg[2*tid+1]));
        bgp[tid] = ub;
    }

    const float* fi = g_bf + ((size_t)b*Nn+i)*40;
    float cxi = fi[0], cyi = fi[1], lwi = fi[2], lhi = fi[3];
    float swi[8], cwi[8], shi[8], chi[8];
#pragma unroll
    for (int f = 0; f < 8; f++) {
        float4 v = *(const float4*)&fi[4 + f*4];
        swi[f]=v.x; cwi[f]=v.y; shi[f]=v.z; chi[f]=v.w;
    }
    __syncthreads();

    const float dm[8] = {1.0f,0.421696503429f,0.177827941004f,0.0749894209332f,
                         0.0316227766017f,0.0133352143216f,0.00562341325190f,0.00237137370566f};
    const float C0 = -6.90775527898f;

#pragma unroll 1
    for (int j = tid; j < Nn; j += 256) {
        const float* fj = g_bf + ((size_t)b*Nn+j)*40;
        float4 h0 = *(const float4*)fj;
        float ux = fmaxf(__logf(fabsf(cxi - h0.x)) - lwi, C0);
        float uy = fmaxf(__logf(fabsf(cyi - h0.y)) - lhi, C0);

        ull acc[8];
#pragma unroll
        for (int p = 0; p < 8; p++) acc[p] = bgp[p];

#pragma unroll
        for (int f = 0; f < 8; f++) {
            float sx, cx_, sy, cy_;
            __sincosf(100.0f*dm[f]*ux, &sx, &cx_);
            __sincosf(100.0f*dm[f]*uy, &sy, &cy_);
            float4 tj = *(const float4*)&fj[4 + f*4];
            float sw_ = swi[f]*tj.y - cwi[f]*tj.x;
            float cw_ = cwi[f]*tj.y + swi[f]*tj.x;
            float sh_ = shi[f]*tj.w - chi[f]*tj.z;
            float ch_ = chi[f]*tj.w + shi[f]*tj.z;
            float sv[4] = {sx, sy, sw_, sh_};
            float cv[4] = {cx_, cy_, cw_, ch_};
#pragma unroll
            for (int c = 0; c < 4; c++) {
                int idx = c*8 + f;
                ull sd = f2dup(sv[c]), cd = f2dup(cv[c]);
                ulonglong2 s0 = *(const ulonglong2*)&Wsp[idx][0];
                ulonglong2 s1 = *(const ulonglong2*)&Wsp[idx][2];
                ulonglong2 s2 = *(const ulonglong2*)&Wsp[idx][4];
                ulonglong2 s3 = *(const ulonglong2*)&Wsp[idx][6];
                acc[0] = ffma2(sd, s0.x, acc[0]); acc[1] = ffma2(sd, s0.y, acc[1]);
                acc[2] = ffma2(sd, s1.x, acc[2]); acc[3] = ffma2(sd, s1.y, acc[3]);
                acc[4] = ffma2(sd, s2.x, acc[4]); acc[5] = ffma2(sd, s2.y, acc[5]);
                acc[6] = ffma2(sd, s3.x, acc[6]); acc[7] = ffma2(sd, s3.y, acc[7]);
                ulonglong2 c0 = *(const ulonglong2*)&Wcp[idx][0];
                ulonglong2 c1 = *(const ulonglong2*)&Wcp[idx][2];
                ulonglong2 c2 = *(const ulonglong2*)&Wcp[idx][4];
                ulonglong2 c3 = *(const ulonglong2*)&Wcp[idx][6];
                acc[0] = ffma2(cd, c0.x, acc[0]); acc[1] = ffma2(cd, c0.y, acc[1]);
                acc[2] = ffma2(cd, c1.x, acc[2]); acc[3] = ffma2(cd, c1.y, acc[3]);
                acc[4] = ffma2(cd, c2.x, acc[4]); acc[5] = ffma2(cd, c2.y, acc[5]);
                acc[6] = ffma2(cd, c3.x, acc[6]); acc[7] = ffma2(cd, c3.y, acc[7]);
            }
        }
#pragma unroll
        for (int p = 0; p < 8; p++) {
            float2 u = unpack2(acc[p]);
            hbuf[2*p][j]   = __float2half_rn(fmaxf(u.x, 1e-6f));
            hbuf[2*p+1][j] = __float2half_rn(fmaxf(u.y, 1e-6f));
        }
    }
    __syncthreads();

    // write phase: ONE contiguous 16 KB burst per block, streaming stores
    __half* gout = &g_g16[((size_t)b*Nn + i) * (size_t)(Hh*Nn)];
    const uint4* src = (const uint4*)&hbuf[0][0];
#pragma unroll 1
    for (int t = tid; t < 1024; t += 256)
        __stcs((uint4*)gout + t, src[t]);
}

// ---------------- flash attention (g layout (b,i,h,j)) ---------------------
__global__ __launch_bounds__(128) void attn_kernel() {
    extern __shared__ float sh[];
    float* Qs = sh;
    float* Kt = sh + 64*68;
    float* Vt = Kt + 64*68;
    float* Pt = Vt + 64*68;

    int bh = blockIdx.y;
    int b = bh >> 4, h = bh & 15;
    int q0 = blockIdx.x * 64;
    const float* Qg = g_q + ((size_t)bh*Nn + q0)*Dk;
    const float* Kg = g_k + (size_t)bh*Nn*Dk;
    const float* Vg = g_v + (size_t)bh*Nn*Dk;
    // g row for query q: g_g16[((b*Nn + q)*Hh + h)*Nn + j]
    const __half* Gg = g_g16 + (((size_t)b*Nn + q0)*Hh + h)*Nn;

    int tid = threadIdx.x;
    int tx = tid & 7, qs = tid >> 3;

    for (int tt = tid; tt < 256; tt += 128) {
        int qb = (tt & 15)*4, d0 = (tt >> 4)*4;
        float4 r0 = *(const float4*)&Qg[(qb+0)*64+d0];
        float4 r1 = *(const float4*)&Qg[(qb+1)*64+d0];
        float4 r2 = *(const float4*)&Qg[(qb+2)*64+d0];
        float4 r3 = *(const float4*)&Qg[(qb+3)*64+d0];
        *(float4*)&Qs[(d0+0)*68+qb] = make_float4(r0.x,r1.x,r2.x,r3.x);
        *(float4*)&Qs[(d0+1)*68+qb] = make_float4(r0.y,r1.y,r2.y,r3.y);
        *(float4*)&Qs[(d0+2)*68+qb] = make_float4(r0.z,r1.z,r2.z,r3.z);
        *(float4*)&Qs[(d0+3)*68+qb] = make_float4(r0.w,r1.w,r2.w,r3.w);
    }

    float m[4], l[4];
    ull o[4][4];
#pragma unroll
    for (int i = 0; i < 4; i++) {
        m[i] = -1e30f; l[i] = 0.f;
#pragma unroll
        for (int p = 0; p < 4; p++) o[i][p] = 0ull;
    }

    for (int kt = 0; kt < 8; kt++) {
        __syncthreads();
        for (int tt = tid; tt < 256; tt += 128) {
            int kb = (tt & 15)*4, d0 = (tt >> 4)*4;
            const float* Kb = Kg + (size_t)(kt*64)*Dk;
            float4 r0 = *(const float4*)&Kb[(kb+0)*64+d0];
            float4 r1 = *(const float4*)&Kb[(kb+1)*64+d0];
            float4 r2 = *(const float4*)&Kb[(kb+2)*64+d0];
            float4 r3 = *(const float4*)&Kb[(kb+3)*64+d0];
            *(float4*)&Kt[(d0+0)*68+kb] = make_float4(r0.x,r1.x,r2.x,r3.x);
            *(float4*)&Kt[(d0+1)*68+kb] = make_float4(r0.y,r1.y,r2.y,r3.y);
            *(float4*)&Kt[(d0+2)*68+kb] = make_float4(r0.z,r1.z,r2.z,r3.z);
            *(float4*)&Kt[(d0+3)*68+kb] = make_float4(r0.w,r1.w,r2.w,r3.w);
        }
        for (int i = tid; i < 1024; i += 128) {
            int r = i >> 4, c = (i & 15)*4;
            *(float4*)&Vt[r*68+c] = *(const float4*)&Vg[(size_t)(kt*64+r)*64+c];
        }
        __syncthreads();

        ull acc[4][4];
#pragma unroll
        for (int i = 0; i < 4; i++)
#pragma unroll
            for (int p = 0; p < 4; p++) acc[i][p] = 0ull;
#pragma unroll 4
        for (int d = 0; d < 64; d++) {
            float4 qv = *(const float4*)&Qs[d*68 + qs*4];
            ull qd[4] = {f2dup(qv.x), f2dup(qv.y), f2dup(qv.z), f2dup(qv.w)};
            ulonglong2 k0 = *(const ulonglong2*)&Kt[d*68 + tx*8];
            ulonglong2 k1 = *(const ulonglong2*)&Kt[d*68 + tx*8 + 4];
            ull kp[4] = {k0.x, k0.y, k1.x, k1.y};
#pragma unroll
            for (int i = 0; i < 4; i++)
#pragma unroll
                for (int p = 0; p < 4; p++)
                    acc[i][p] = ffma2(qd[i], kp[p], acc[i][p]);
        }

#pragma unroll
        for (int qq = 0; qq < 4; qq++) {
            float s[8];
#pragma unroll
            for (int p = 0; p < 4; p++) {
                float2 u = unpack2(acc[qq][p]);
                s[2*p] = u.x*0.125f; s[2*p+1] = u.y*0.125f;
            }
            float mt = s[0];
#pragma unroll
            for (int j = 1; j < 8; j++) mt = fmaxf(mt, s[j]);
            mt = fmaxf(mt, __shfl_xor_sync(0xffffffffu, mt, 1, 8));
            mt = fmaxf(mt, __shfl_xor_sync(0xffffffffu, mt, 2, 8));
            mt = fmaxf(mt, __shfl_xor_sync(0xffffffffu, mt, 4, 8));
            float mn = fmaxf(m[qq], mt);
            float resc = __expf(m[qq] - mn);
            m[qq] = mn;
            l[qq] *= resc;
            ull rd = f2dup(resc);
#pragma unroll
            for (int p = 0; p < 4; p++) o[qq][p] = fmul2(o[qq][p], rd);

            const __half* gp = Gg + (size_t)(qs*4+qq)*(Hh*Nn) + kt*64 + tx*8;
            uint4 gv = *(const uint4*)gp;
            float2 g0 = __half22float2(*(__half2*)&gv.x);
            float2 g1 = __half22float2(*(__half2*)&gv.y);
            float2 g2 = __half22float2(*(__half2*)&gv.z);
            float2 g3 = __half22float2(*(__half2*)&gv.w);
            float w0 = g0.x*__expf(s[0]-mn), w1 = g0.y*__expf(s[1]-mn);
            float w2 = g1.x*__expf(s[2]-mn), w3 = g1.y*__expf(s[3]-mn);
            float w4 = g2.x*__expf(s[4]-mn), w5 = g2.y*__expf(s[5]-mn);
            float w6 = g3.x*__expf(s[6]-mn), w7 = g3.y*__expf(s[7]-mn);
            float ps = ((w0+w1)+(w2+w3)) + ((w4+w5)+(w6+w7));
            ps += __shfl_xor_sync(0xffffffffu, ps, 1, 8);
            ps += __shfl_xor_sync(0xffffffffu, ps, 2, 8);
            ps += __shfl_xor_sync(0xffffffffu, ps, 4, 8);
            l[qq] += ps;
            *(float4*)&Pt[(qs*4+qq)*72 + tx*8]     = make_float4(w0,w1,w2,w3);
            *(float4*)&Pt[(qs*4+qq)*72 + tx*8 + 4] = make_float4(w4,w5,w6,w7);
        }
        __syncthreads();

#pragma unroll 4
        for (int k = 0; k < 64; k++) {
            ull pd[4];
#pragma unroll
            for (int qq = 0; qq < 4; qq++) pd[qq] = f2dup(Pt[(qs*4+qq)*72 + k]);
            ulonglong2 v0 = *(const ulonglong2*)&Vt[k*68 + tx*8];
            ulonglong2 v1 = *(const ulonglong2*)&Vt[k*68 + tx*8 + 4];
            ull vp[4] = {v0.x, v0.y, v1.x, v1.y};
#pragma unroll
            for (int i = 0; i < 4; i++)
#pragma unroll
                for (int p = 0; p < 4; p++)
                    o[i][p] = ffma2(pd[i], vp[p], o[i][p]);
        }
    }

#pragma unroll
    for (int qq = 0; qq < 4; qq++) {
        float inv = 1.0f / l[qq];
        int row = q0 + qs*4 + qq;
        float2 u0 = unpack2(o[qq][0]), u1 = unpack2(o[qq][1]);
        float2 u2 = unpack2(o[qq][2]), u3 = unpack2(o[qq][3]);
        size_t base = ((size_t)b*Nn+row)*Dm + h*64 + tx*8;
        *(float4*)&g_attn[base]   = make_float4(u0.x*inv, u0.y*inv, u1.x*inv, u1.y*inv);
        *(float4*)&g_attn[base+4] = make_float4(u2.x*inv, u2.y*inv, u3.x*inv, u3.y*inv);
    }
}

// ---------------------------------------------------------------------------
extern "C" void kernel_launch(void* const* d_in, const int* in_sizes, int n_in,
                              void* d_out, int out_size) {
    (void)in_sizes; (void)n_in; (void)out_size;
    const float* queries = (const float*)d_in[0];
    const float* keys    = (const float*)d_in[1];
    const float* values  = (const float*)d_in[2];
    const float* boxes   = (const float*)d_in[3];
    const float* Wq = (const float*)d_in[4];
    const float* bq = (const float*)d_in[5];
    const float* Wk = (const float*)d_in[6];
    const float* bk = (const float*)d_in[7];
    const float* Wv = (const float*)d_in[8];
    const float* bv = (const float*)d_in[9];
    const float* Wo = (const float*)d_in[10];
    const float* bo = (const float*)d_in[11];
    const float* Wg = (const float*)d_in[12];
    const float* bg = (const float*)d_in[13];
    float* out = (float*)d_out;

    float *dattn = nullptr;
    cudaGetSymbolAddress((void**)&dattn, g_attn);

    size_t shb = (size_t)(64*68*3 + 64*72) * sizeof(float);
    cudaFuncSetAttribute(attn_kernel, cudaFuncAttributeMaxDynamicSharedMemorySize, (int)shb);

    dim3 gemm_grid(Dm/128, (Bb*Nn)/128);

    // launch order: box(1), q(2), kv(3), geo(4) <- ncu slot, attn(5), out(6)
    box_feat_kernel<<<Bb, 512>>>(boxes);
    sgemm_qkv<<<dim3(8, 32, 1), 256>>>(queries, keys, values, Wq, Wk, Wv, bq, bk, bv, 0);
    sgemm_qkv<<<dim3(8, 32, 2), 256>>>(queries, keys, values, Wq, Wk, Wv, bq, bk, bv, 1);
    geo_bias_kernel<<<dim3(Nn, Bb), 256>>>(Wg, bg);
    attn_kernel<<<dim3(Nn/64, Bb*Hh), 128, shb>>>();
    sgemm_tn<<<gemm_grid, 256>>>(dattn, Wo, bo, out);
}